// round 2
// baseline (speedup 1.0000x reference)
#include <cuda_runtime.h>
#include <math.h>

#define VOCAB 50000
#define D 300
#define S 5
#define CTX 10
#define B 16384
#define XCOLS (2 + CTX)

#define THREADS 256
#define NBLOCKS ((B * 32) / THREADS)   // one warp per batch element -> 2048 blocks

// Scratch (no device allocs allowed). Zero-initialized at module load;
// g_count is reset to 0 by the last block each call -> graph-replay safe.
__device__ float g_part[NBLOCKS * S];
__device__ unsigned int g_count;

__global__ __launch_bounds__(THREADS) void sense_fused_kernel(
    const int* __restrict__ x,
    const float* __restrict__ Wg,
    const float* __restrict__ Ws,
    float* __restrict__ out)
{
    const int gwarp = (blockIdx.x * THREADS + threadIdx.x) >> 5;
    const int lane  = threadIdx.x & 31;

    __shared__ float ssum[S];
    if (threadIdx.x < S) ssum[threadIdx.x] = 0.0f;
    __syncthreads();

    float sc[S] = {0.f, 0.f, 0.f, 0.f, 0.f};

    {
        const int* xr = x + gwarp * XCOLS;
        const int x0 = __ldg(&xr[0]);

        const bool has3 = (lane + 64) < 75;   // 75 float4 chunks per 300-float row

        float4 c0 = make_float4(0.f, 0.f, 0.f, 0.f);
        float4 c1 = make_float4(0.f, 0.f, 0.f, 0.f);
        float4 c2 = make_float4(0.f, 0.f, 0.f, 0.f);

        // Context sum: W_g rows get ~3.3x reuse across the batch -> default
        // caching (keep in L2).
        #pragma unroll
        for (int j = 0; j < CTX; j++) {
            const int w = __ldg(&xr[2 + j]);
            const float4* row = (const float4*)(Wg + (size_t)w * D);
            float4 r0 = __ldg(&row[lane]);
            float4 r1 = __ldg(&row[lane + 32]);
            c0.x += r0.x; c0.y += r0.y; c0.z += r0.z; c0.w += r0.w;
            c1.x += r1.x; c1.y += r1.y; c1.z += r1.z; c1.w += r1.w;
            if (has3) {
                float4 r2 = __ldg(&row[lane + 64]);
                c2.x += r2.x; c2.y += r2.y; c2.z += r2.z; c2.w += r2.w;
            }
        }

        // Sense rows: ~1.2x reuse, 84MB unique footprint -> stream (evict-first)
        // so they don't evict the L2-resident W_g working set.
        #pragma unroll
        for (int s = 0; s < S; s++) {
            const float4* row = (const float4*)(Ws + ((size_t)x0 * S + s) * D);
            float4 r0 = __ldcs(&row[lane]);
            float4 r1 = __ldcs(&row[lane + 32]);
            float p = r0.x * c0.x + r0.y * c0.y + r0.z * c0.z + r0.w * c0.w;
            p += r1.x * c1.x + r1.y * c1.y + r1.z * c1.z + r1.w * c1.w;
            if (has3) {
                float4 r2 = __ldcs(&row[lane + 64]);
                p += r2.x * c2.x + r2.y * c2.y + r2.z * c2.z + r2.w * c2.w;
            }
            #pragma unroll
            for (int o = 16; o > 0; o >>= 1)
                p += __shfl_xor_sync(0xFFFFFFFFu, p, o);
            sc[s] = p;
        }
    }

    // block combine
    if (lane == 0) {
        #pragma unroll
        for (int s = 0; s < S; s++)
            atomicAdd(&ssum[s], sc[s]);
    }
    __syncthreads();

    // write this block's partial (plain store, no init needed)
    if (threadIdx.x < S)
        g_part[blockIdx.x * S + threadIdx.x] = ssum[threadIdx.x];

    // last-block reduction + sigmoid + counter reset (graph-replay safe)
    __threadfence();
    __shared__ bool is_last;
    if (threadIdx.x == 0) {
        unsigned int ticket = atomicAdd(&g_count, 1u);
        is_last = (ticket == (unsigned int)(NBLOCKS - 1));
    }
    __syncthreads();

    if (is_last) {
        float acc[S] = {0.f, 0.f, 0.f, 0.f, 0.f};
        for (int i = threadIdx.x; i < NBLOCKS; i += THREADS) {
            #pragma unroll
            for (int s = 0; s < S; s++)
                acc[s] += g_part[i * S + s];
        }
        __shared__ float fin[S];
        if (threadIdx.x < S) fin[threadIdx.x] = 0.0f;
        __syncthreads();
        #pragma unroll
        for (int s = 0; s < S; s++)
            atomicAdd(&fin[s], acc[s]);
        __syncthreads();
        if (threadIdx.x < S)
            out[threadIdx.x] = 1.0f / (1.0f + expf(-fin[threadIdx.x]));
        if (threadIdx.x == 0)
            g_count = 0;   // reset for next graph replay
    }
}

extern "C" void kernel_launch(void* const* d_in, const int* in_sizes, int n_in,
                              void* d_out, int out_size) {
    const int*   x  = (const int*)d_in[0];
    const float* Wg = (const float*)d_in[1];
    const float* Ws = (const float*)d_in[2];
    float* out = (float*)d_out;

    sense_fused_kernel<<<NBLOCKS, THREADS>>>(x, Wg, Ws, out);
}

// round 3
// speedup vs baseline: 1.4781x; 1.4781x over previous
#include <cuda_runtime.h>
#include <math.h>

#define VOCAB 50000
#define D 300
#define S 5
#define CTX 10
#define B 16384
#define XCOLS (2 + CTX)

#define THREADS 256
#define NBLOCKS ((B * 32) / THREADS)   // one warp per batch element -> 2048 blocks

// Per-block partials (plain stores each call -> no init kernel needed).
__device__ float g_part[NBLOCKS * S];

__global__ __launch_bounds__(THREADS) void sense_main_kernel(
    const int* __restrict__ x,
    const float* __restrict__ Wg,
    const float* __restrict__ Ws)
{
    const int gwarp = (blockIdx.x * THREADS + threadIdx.x) >> 5;
    const int lane  = threadIdx.x & 31;

    __shared__ float ssum[S];
    if (threadIdx.x < S) ssum[threadIdx.x] = 0.0f;
    __syncthreads();

    float sc[S] = {0.f, 0.f, 0.f, 0.f, 0.f};

    {
        const int* xr = x + gwarp * XCOLS;
        const int x0 = __ldg(&xr[0]);

        const bool has3 = (lane + 64) < 75;   // 75 float4 chunks per 300-float row

        float4 c0 = make_float4(0.f, 0.f, 0.f, 0.f);
        float4 c1 = make_float4(0.f, 0.f, 0.f, 0.f);
        float4 c2 = make_float4(0.f, 0.f, 0.f, 0.f);

        #pragma unroll
        for (int j = 0; j < CTX; j++) {
            const int w = __ldg(&xr[2 + j]);
            const float4* row = (const float4*)(Wg + (size_t)w * D);
            float4 r0 = row[lane];
            float4 r1 = row[lane + 32];
            c0.x += r0.x; c0.y += r0.y; c0.z += r0.z; c0.w += r0.w;
            c1.x += r1.x; c1.y += r1.y; c1.z += r1.z; c1.w += r1.w;
            if (has3) {
                float4 r2 = row[lane + 64];
                c2.x += r2.x; c2.y += r2.y; c2.z += r2.z; c2.w += r2.w;
            }
        }

        #pragma unroll
        for (int s = 0; s < S; s++) {
            const float4* row = (const float4*)(Ws + ((size_t)x0 * S + s) * D);
            float4 r0 = row[lane];
            float4 r1 = row[lane + 32];
            float p = r0.x * c0.x + r0.y * c0.y + r0.z * c0.z + r0.w * c0.w;
            p += r1.x * c1.x + r1.y * c1.y + r1.z * c1.z + r1.w * c1.w;
            if (has3) {
                float4 r2 = row[lane + 64];
                p += r2.x * c2.x + r2.y * c2.y + r2.z * c2.z + r2.w * c2.w;
            }
            #pragma unroll
            for (int o = 16; o > 0; o >>= 1)
                p += __shfl_xor_sync(0xFFFFFFFFu, p, o);
            sc[s] = p;
        }
    }

    // block combine via shared atomics (8 warps x 5)
    if (lane == 0) {
        #pragma unroll
        for (int s = 0; s < S; s++)
            atomicAdd(&ssum[s], sc[s]);
    }
    __syncthreads();

    // plain store of this block's partial — no global atomics, no fence
    if (threadIdx.x < S)
        g_part[blockIdx.x * S + threadIdx.x] = ssum[threadIdx.x];
}

__global__ __launch_bounds__(256) void finalize_kernel(float* __restrict__ out) {
    float acc[S] = {0.f, 0.f, 0.f, 0.f, 0.f};
    // NBLOCKS=2048, 256 threads -> 8 strided iterations, float4-ish pattern
    for (int i = threadIdx.x; i < NBLOCKS; i += 256) {
        #pragma unroll
        for (int s = 0; s < S; s++)
            acc[s] += g_part[i * S + s];
    }
    __shared__ float fin[S];
    if (threadIdx.x < S) fin[threadIdx.x] = 0.0f;
    __syncthreads();
    // warp-reduce each accumulator first to cut shared atomics 32x
    #pragma unroll
    for (int s = 0; s < S; s++) {
        float v = acc[s];
        #pragma unroll
        for (int o = 16; o > 0; o >>= 1)
            v += __shfl_xor_sync(0xFFFFFFFFu, v, o);
        if ((threadIdx.x & 31) == 0)
            atomicAdd(&fin[s], v);
    }
    __syncthreads();
    if (threadIdx.x < S)
        out[threadIdx.x] = 1.0f / (1.0f + expf(-fin[threadIdx.x]));
}

extern "C" void kernel_launch(void* const* d_in, const int* in_sizes, int n_in,
                              void* d_out, int out_size) {
    const int*   x  = (const int*)d_in[0];
    const float* Wg = (const float*)d_in[1];
    const float* Ws = (const float*)d_in[2];
    float* out = (float*)d_out;

    sense_main_kernel<<<NBLOCKS, THREADS>>>(x, Wg, Ws);
    finalize_kernel<<<1, 256>>>(out);
}

// round 4
// speedup vs baseline: 1.6706x; 1.1303x over previous
#include <cuda_runtime.h>
#include <math.h>

#define VOCAB 50000
#define D 300
#define S 5
#define CTX 10
#define B 16384
#define XCOLS (2 + CTX)

#define THREADS 256
#define NBLOCKS ((B * 32) / THREADS)   // one warp per batch element -> 2048 blocks

// Accumulator: zero at module load; finalize_kernel resets it to 0 after each
// read, so every kernel_launch call (including graph replays) starts from 0.
__device__ float g_acc[S];

__global__ __launch_bounds__(THREADS) void sense_main_kernel(
    const int* __restrict__ x,
    const float* __restrict__ Wg,
    const float* __restrict__ Ws)
{
    const int gwarp = (blockIdx.x * THREADS + threadIdx.x) >> 5;
    const int lane  = threadIdx.x & 31;

    __shared__ float ssum[S];
    if (threadIdx.x < S) ssum[threadIdx.x] = 0.0f;
    __syncthreads();

    float sc[S] = {0.f, 0.f, 0.f, 0.f, 0.f};

    {
        const int* xr = x + gwarp * XCOLS;
        const int x0 = __ldg(&xr[0]);

        const bool has3 = (lane + 64) < 75;   // 75 float4 chunks per 300-float row

        float4 c0 = make_float4(0.f, 0.f, 0.f, 0.f);
        float4 c1 = make_float4(0.f, 0.f, 0.f, 0.f);
        float4 c2 = make_float4(0.f, 0.f, 0.f, 0.f);

        #pragma unroll
        for (int j = 0; j < CTX; j++) {
            const int w = __ldg(&xr[2 + j]);
            const float4* row = (const float4*)(Wg + (size_t)w * D);
            float4 r0 = row[lane];
            float4 r1 = row[lane + 32];
            c0.x += r0.x; c0.y += r0.y; c0.z += r0.z; c0.w += r0.w;
            c1.x += r1.x; c1.y += r1.y; c1.z += r1.z; c1.w += r1.w;
            if (has3) {
                float4 r2 = row[lane + 64];
                c2.x += r2.x; c2.y += r2.y; c2.z += r2.z; c2.w += r2.w;
            }
        }

        #pragma unroll
        for (int s = 0; s < S; s++) {
            const float4* row = (const float4*)(Ws + ((size_t)x0 * S + s) * D);
            float4 r0 = row[lane];
            float4 r1 = row[lane + 32];
            float p = r0.x * c0.x + r0.y * c0.y + r0.z * c0.z + r0.w * c0.w;
            p += r1.x * c1.x + r1.y * c1.y + r1.z * c1.z + r1.w * c1.w;
            if (has3) {
                float4 r2 = row[lane + 64];
                p += r2.x * c2.x + r2.y * c2.y + r2.z * c2.z + r2.w * c2.w;
            }
            #pragma unroll
            for (int o = 16; o > 0; o >>= 1)
                p += __shfl_xor_sync(0xFFFFFFFFu, p, o);
            sc[s] = p;
        }
    }

    // block combine via shared atomics (8 warps x 5)
    if (lane == 0) {
        #pragma unroll
        for (int s = 0; s < S; s++)
            atomicAdd(&ssum[s], sc[s]);
    }
    __syncthreads();

    // one global atomicAdd per block per sense (10240 total to 5 addresses)
    if (threadIdx.x < S)
        atomicAdd(&g_acc[threadIdx.x], ssum[threadIdx.x]);
}

__global__ void finalize_kernel(float* __restrict__ out) {
    if (threadIdx.x < S) {
        float v = g_acc[threadIdx.x];
        out[threadIdx.x] = 1.0f / (1.0f + expf(-v));
        g_acc[threadIdx.x] = 0.0f;   // reset for the next call / graph replay
    }
}

extern "C" void kernel_launch(void* const* d_in, const int* in_sizes, int n_in,
                              void* d_out, int out_size) {
    const int*   x  = (const int*)d_in[0];
    const float* Wg = (const float*)d_in[1];
    const float* Ws = (const float*)d_in[2];
    float* out = (float*)d_out;

    sense_main_kernel<<<NBLOCKS, THREADS>>>(x, Wg, Ws);
    finalize_kernel<<<1, 32>>>(out);
}